// round 15
// baseline (speedup 1.0000x reference)
#include <cuda_runtime.h>
#include <cstdint>

#define CASCADES 3
#define GS3 16777216              // 256^3 cells per cascade
#define NCOORD 4194304            // GS3 / 4 coords per cascade
#define TOTAL_CELLS (CASCADES * GS3)          // 50331648
#define BITS_BYTES  (TOTAL_CELLS / 8)         // 6291456

// Scratch: per-cell winner = (coord_index + 1), 0 = no write.
__device__ unsigned g_win[TOTAL_CELLS];

__device__ __forceinline__ unsigned p1b2(unsigned x) {
    x &= 0x3FFu;
    x = (x | (x << 16)) & 0x030000FFu;
    x = (x | (x << 8))  & 0x0300F00Fu;
    x = (x | (x << 4))  & 0x030C30C3u;
    x = (x | (x << 2))  & 0x09249249u;
    return x;
}
__device__ __forceinline__ unsigned morton(unsigned x, unsigned y, unsigned z) {
    return p1b2(x) | (p1b2(y) << 1) | (p1b2(z) << 2);
}

__global__ void zero_k(uint4* __restrict__ p, int n4) {
    int i = blockIdx.x * blockDim.x + threadIdx.x;
    if (i < n4) p[i] = make_uint4(0u, 0u, 0u, 0u);
}

// 4 coords per thread: 3 x int4 streaming loads, 4 fire-and-forget RED.MAX.
__global__ void scatter_k(const int4* __restrict__ coords4,
                          unsigned* __restrict__ win) {
    int t = blockIdx.x * blockDim.x + threadIdx.x;   // t < NCOORD/4
    if (t >= NCOORD / 4) return;
    int4 a = __ldcs(coords4 + 3 * t + 0);
    int4 b = __ldcs(coords4 + 3 * t + 1);
    int4 c = __ldcs(coords4 + 3 * t + 2);
    unsigned base = 4u * (unsigned)t;
    unsigned m0 = morton((unsigned)a.x, (unsigned)a.y, (unsigned)a.z);
    unsigned m1 = morton((unsigned)a.w, (unsigned)b.x, (unsigned)b.y);
    unsigned m2 = morton((unsigned)b.z, (unsigned)b.w, (unsigned)c.x);
    unsigned m3 = morton((unsigned)c.y, (unsigned)c.z, (unsigned)c.w);
    // last-write-wins: highest coord index wins (matches sequential scatter)
    atomicMax(win + m0, base + 1u);
    atomicMax(win + m1, base + 2u);
    atomicMax(win + m2, base + 3u);
    atomicMax(win + m3, base + 4u);
}

// R14-form combine: 8 cells/thread, plain loads/stores, hoisted gathers.
template <int FLOATBITS>
__global__ void combine_k(const float* __restrict__ density,
                          const float* __restrict__ sigmas,
                          const unsigned* __restrict__ win,
                          float* __restrict__ out_grid,
                          uint8_t* __restrict__ out_bits_u8,
                          float* __restrict__ out_bits_f) {
    int t = blockIdx.x * blockDim.x + threadIdx.x;   // one byte (8 cells)
    if (t >= GS3 / 8) return;

    uint4 w0 = ((const uint4*)win)[2 * t + 0];
    uint4 w1 = ((const uint4*)win)[2 * t + 1];
    float4 d0 = ((const float4*)density)[2 * t + 0];
    float4 d1 = ((const float4*)density)[2 * t + 1];

    unsigned ws[8] = {w0.x, w0.y, w0.z, w0.w, w1.x, w1.y, w1.z, w1.w};
    float    dv[8] = {d0.x, d0.y, d0.z, d0.w, d1.x, d1.y, d1.z, d1.w};

    // Hoisted gathers: 8 independent predicated loads, maximum gather MLP.
    float sg[8];
#pragma unroll
    for (int b = 0; b < 8; b++)
        sg[b] = ws[b] ? __ldg(sigmas + (ws[b] - 1u)) : -1.0f;

    float    v[8];
    unsigned byte = 0u;
#pragma unroll
    for (int b = 0; b < 8; b++) {
        float val = dv[b];
        if (ws[b]) {
            float s = sg[b];                      // DENSITY_SCALE == 1.0
            if (val >= 0.0f && s >= 0.0f)         // valid = old>=0 && new>=0
                val = fmaxf(0.95f * val, s);      // DECAY = 0.95
        }
        v[b] = val;
        if (val > 0.01f) byte |= (1u << b);       // DENSITY_THRESHOLD = 0.01
    }

    ((float4*)out_grid)[2 * t + 0] = make_float4(v[0], v[1], v[2], v[3]);
    ((float4*)out_grid)[2 * t + 1] = make_float4(v[4], v[5], v[6], v[7]);

    if (FLOATBITS) {
        out_bits_f[t] = (float)byte;
    } else {
        out_bits_u8[t] = (uint8_t)byte;
    }
}

extern "C" void kernel_launch(void* const* d_in, const int* in_sizes, int n_in,
                              void* d_out, int out_size) {
    const float* density = (const float*)d_in[0];   // [3, 256^3] f32
    const float* sigmas  = (const float*)d_in[1];   // [3, NCOORD] f32
    const int*   coords  = (const int*)d_in[2];     // [3, NCOORD, 3] i32

    unsigned* win = nullptr;
    cudaGetSymbolAddress((void**)&win, g_win);

    const long long f32_elems = (long long)TOTAL_CELLS + (long long)BITS_BYTES;
    bool floatbits = ((long long)out_size == f32_elems);

    float*   out_grid = (float*)d_out;
    uint8_t* bits_u8  = (uint8_t*)d_out + (size_t)TOTAL_CELLS * 4;
    float*   bits_f   = (float*)d_out + (size_t)TOTAL_CELLS;

    const int ZB = (GS3 / 4) / 256;      // zero blocks
    const int SB = (NCOORD / 4) / 256;   // scatter blocks
    const int CB = (GS3 / 8) / 256;      // combine blocks

    // Side stream + events for zero-only overlap: zero(c+1) runs under
    // combine(c). Scatter is NEVER overlapped (R6: atomic RMW overlap lost).
    static cudaStream_t s1 = nullptr;
    static cudaEvent_t evf0, evf1, evz1, evz2;
    if (!s1) {
        cudaStreamCreateWithFlags(&s1, cudaStreamNonBlocking);
        cudaEventCreateWithFlags(&evf0, cudaEventDisableTiming);
        cudaEventCreateWithFlags(&evf1, cudaEventDisableTiming);
        cudaEventCreateWithFlags(&evz1, cudaEventDisableTiming);
        cudaEventCreateWithFlags(&evz2, cudaEventDisableTiming);
    }

    unsigned* w0 = win;
    unsigned* w1 = win + (size_t)GS3;
    unsigned* w2 = win + (size_t)2 * GS3;

    auto launch_scatter = [&](int c) {
        scatter_k<<<SB, 256>>>(
            (const int4*)(coords + (size_t)c * NCOORD * 3),
            win + (size_t)c * GS3);
    };
    auto launch_combine = [&](int c) {
        const float* denc = density + (size_t)c * GS3;
        const float* sigc = sigmas + (size_t)c * NCOORD;
        const unsigned* winc = win + (size_t)c * GS3;
        if (floatbits)
            combine_k<1><<<CB, 256>>>(denc, sigc, winc,
                                      out_grid + (size_t)c * GS3, nullptr,
                                      bits_f + (size_t)c * (GS3 / 8));
        else
            combine_k<0><<<CB, 256>>>(denc, sigc, winc,
                                      out_grid + (size_t)c * GS3,
                                      bits_u8 + (size_t)c * (GS3 / 8),
                                      nullptr);
    };

    // s0: zero0, scatter0
    zero_k<<<ZB, 256>>>((uint4*)w0, GS3 / 4);
    launch_scatter(0);
    cudaEventRecord(evf0, 0);            // fork point (after scatter0)

    // s1: zero1 concurrent with combine0
    cudaStreamWaitEvent(s1, evf0, 0);
    zero_k<<<ZB, 256, 0, s1>>>((uint4*)w1, GS3 / 4);
    cudaEventRecord(evz1, s1);

    // s0: combine0; then scatter1 (needs zero1 done)
    launch_combine(0);
    cudaStreamWaitEvent(0, evz1, 0);
    launch_scatter(1);
    cudaEventRecord(evf1, 0);            // fork point (after scatter1)

    // s1: zero2 concurrent with combine1
    cudaStreamWaitEvent(s1, evf1, 0);
    zero_k<<<ZB, 256, 0, s1>>>((uint4*)w2, GS3 / 4);
    cudaEventRecord(evz2, s1);

    // s0: combine1; scatter2 (needs zero2); combine2. Join: s0 consumes evz2,
    // so the capture ends with a single leaf on s0.
    launch_combine(1);
    cudaStreamWaitEvent(0, evz2, 0);
    launch_scatter(2);
    launch_combine(2);
}

// round 16
// speedup vs baseline: 1.0935x; 1.0935x over previous
#include <cuda_runtime.h>
#include <cstdint>

#define CASCADES 3
#define GS3 16777216              // 256^3 cells per cascade
#define NCOORD 4194304            // GS3 / 4 coords per cascade
#define TOTAL_CELLS (CASCADES * GS3)          // 50331648
#define BITS_BYTES  (TOTAL_CELLS / 8)         // 6291456

// Scratch: per-cell winner = (coord_index + 1), 0 = no write.
// Zeroed per-cascade immediately before scatter: the zero->scatter->combine
// chain must stay serial and adjacent so the 64MB region lives in L2 for its
// whole lifetime (overlap breaks the absorption: R6/R15 measured +18..+36us).
__device__ unsigned g_win[TOTAL_CELLS];

__device__ __forceinline__ unsigned p1b2(unsigned x) {
    x &= 0x3FFu;
    x = (x | (x << 16)) & 0x030000FFu;
    x = (x | (x << 8))  & 0x0300F00Fu;
    x = (x | (x << 4))  & 0x030C30C3u;
    x = (x | (x << 2))  & 0x09249249u;
    return x;
}
__device__ __forceinline__ unsigned morton(unsigned x, unsigned y, unsigned z) {
    return p1b2(x) | (p1b2(y) << 1) | (p1b2(z) << 2);
}

// 64 bytes per thread: 4 unrolled STG.128. Quarter the threads/launch ramp of
// the 16B/thread version; stores are fire-and-forget so low occ is fine.
__global__ void zero_k(uint4* __restrict__ p, int n4) {
    int i = blockIdx.x * blockDim.x + threadIdx.x;   // i < n4/4
    uint4 z = make_uint4(0u, 0u, 0u, 0u);
    uint4* q = p + 4 * i;
#pragma unroll
    for (int k = 0; k < 4; k++) q[k] = z;
}

// 4 coords per thread: 3 x int4 streaming loads, 4 fire-and-forget RED.MAX.
// (R1 form; at the REDG spread-address issue floor.)
__global__ void scatter_k(const int4* __restrict__ coords4,
                          unsigned* __restrict__ win) {
    int t = blockIdx.x * blockDim.x + threadIdx.x;   // t < NCOORD/4
    if (t >= NCOORD / 4) return;
    int4 a = __ldcs(coords4 + 3 * t + 0);
    int4 b = __ldcs(coords4 + 3 * t + 1);
    int4 c = __ldcs(coords4 + 3 * t + 2);
    unsigned base = 4u * (unsigned)t;
    unsigned m0 = morton((unsigned)a.x, (unsigned)a.y, (unsigned)a.z);
    unsigned m1 = morton((unsigned)a.w, (unsigned)b.x, (unsigned)b.y);
    unsigned m2 = morton((unsigned)b.z, (unsigned)b.w, (unsigned)c.x);
    unsigned m3 = morton((unsigned)c.y, (unsigned)c.z, (unsigned)c.w);
    // last-write-wins: highest coord index wins (matches sequential scatter)
    atomicMax(win + m0, base + 1u);
    atomicMax(win + m1, base + 2u);
    atomicMax(win + m2, base + 3u);
    atomicMax(win + m3, base + 4u);
}

// R14-form combine: 8 cells/thread, plain loads/stores, hoisted gathers.
template <int FLOATBITS>
__global__ void combine_k(const float* __restrict__ density,
                          const float* __restrict__ sigmas,
                          const unsigned* __restrict__ win,
                          float* __restrict__ out_grid,
                          uint8_t* __restrict__ out_bits_u8,
                          float* __restrict__ out_bits_f) {
    int t = blockIdx.x * blockDim.x + threadIdx.x;   // one byte (8 cells)
    if (t >= GS3 / 8) return;

    uint4 w0 = ((const uint4*)win)[2 * t + 0];
    uint4 w1 = ((const uint4*)win)[2 * t + 1];
    float4 d0 = ((const float4*)density)[2 * t + 0];
    float4 d1 = ((const float4*)density)[2 * t + 1];

    unsigned ws[8] = {w0.x, w0.y, w0.z, w0.w, w1.x, w1.y, w1.z, w1.w};
    float    dv[8] = {d0.x, d0.y, d0.z, d0.w, d1.x, d1.y, d1.z, d1.w};

    // Hoisted gathers: 8 independent predicated loads, maximum gather MLP.
    float sg[8];
#pragma unroll
    for (int b = 0; b < 8; b++)
        sg[b] = ws[b] ? __ldg(sigmas + (ws[b] - 1u)) : -1.0f;

    float    v[8];
    unsigned byte = 0u;
#pragma unroll
    for (int b = 0; b < 8; b++) {
        float val = dv[b];
        if (ws[b]) {
            float s = sg[b];                      // DENSITY_SCALE == 1.0
            if (val >= 0.0f && s >= 0.0f)         // valid = old>=0 && new>=0
                val = fmaxf(0.95f * val, s);      // DECAY = 0.95
        }
        v[b] = val;
        if (val > 0.01f) byte |= (1u << b);       // DENSITY_THRESHOLD = 0.01
    }

    ((float4*)out_grid)[2 * t + 0] = make_float4(v[0], v[1], v[2], v[3]);
    ((float4*)out_grid)[2 * t + 1] = make_float4(v[4], v[5], v[6], v[7]);

    if (FLOATBITS) {
        out_bits_f[t] = (float)byte;
    } else {
        out_bits_u8[t] = (uint8_t)byte;
    }
}

extern "C" void kernel_launch(void* const* d_in, const int* in_sizes, int n_in,
                              void* d_out, int out_size) {
    const float* density = (const float*)d_in[0];   // [3, 256^3] f32
    const float* sigmas  = (const float*)d_in[1];   // [3, NCOORD] f32
    const int*   coords  = (const int*)d_in[2];     // [3, NCOORD, 3] i32

    unsigned* win = nullptr;
    cudaGetSymbolAddress((void**)&win, g_win);

    // Output layout: reference returns (new_grid f32, bitfield u8).
    const long long f32_elems = (long long)TOTAL_CELLS + (long long)BITS_BYTES;
    bool floatbits = ((long long)out_size == f32_elems);

    float*   out_grid = (float*)d_out;
    uint8_t* bits_u8  = (uint8_t*)d_out + (size_t)TOTAL_CELLS * 4;
    float*   bits_f   = (float*)d_out + (size_t)TOTAL_CELLS;

    const int ZB = (GS3 / 16) / 256;     // zero blocks (64B/thread) = 4096
    const int SB = (NCOORD / 4) / 256;   // scatter blocks (4 coords/thread)
    const int CB = (GS3 / 8) / 256;      // combine blocks (8 cells/thread)

    // Serial per-cascade pipeline on ONE stream — the measured optimum.
    // (All concurrency variants lost: R6 +18us, R15 +36us; merged phases
    // R9 +65us; fused reset R13 +140us.)
    for (int c = 0; c < CASCADES; c++) {
        unsigned*    winc = win + (size_t)c * GS3;
        const float* denc = density + (size_t)c * GS3;
        const float* sigc = sigmas + (size_t)c * NCOORD;
        const int4*  crdc = (const int4*)(coords + (size_t)c * NCOORD * 3);

        zero_k<<<ZB, 256>>>((uint4*)winc, GS3 / 4);
        scatter_k<<<SB, 256>>>(crdc, winc);
        if (floatbits) {
            combine_k<1><<<CB, 256>>>(denc, sigc, winc,
                                      out_grid + (size_t)c * GS3,
                                      nullptr,
                                      bits_f + (size_t)c * (GS3 / 8));
        } else {
            combine_k<0><<<CB, 256>>>(denc, sigc, winc,
                                      out_grid + (size_t)c * GS3,
                                      bits_u8 + (size_t)c * (GS3 / 8),
                                      nullptr);
        }
    }
}

// round 17
// speedup vs baseline: 1.1587x; 1.0597x over previous
#include <cuda_runtime.h>
#include <cstdint>

#define CASCADES 3
#define GS3 16777216              // 256^3 cells per cascade
#define NCOORD 4194304            // GS3 / 4 coords per cascade
#define TOTAL_CELLS (CASCADES * GS3)          // 50331648
#define BITS_BYTES  (TOTAL_CELLS / 8)         // 6291456

// Scratch: per-cell winner = (coord_index + 1), 0 = no write.
// Zero->scatter->combine must run serial and adjacent per cascade so the
// 64MB region stays L2-resident for its lifetime (R6/R9/R15 all measured
// losses when this chain was broken).
__device__ unsigned g_win[TOTAL_CELLS];

__device__ __forceinline__ unsigned p1b2(unsigned x) {
    x &= 0x3FFu;
    x = (x | (x << 16)) & 0x030000FFu;
    x = (x | (x << 8))  & 0x0300F00Fu;
    x = (x | (x << 4))  & 0x030C30C3u;
    x = (x | (x << 2))  & 0x09249249u;
    return x;
}
__device__ __forceinline__ unsigned morton(unsigned x, unsigned y, unsigned z) {
    return p1b2(x) | (p1b2(y) << 1) | (p1b2(z) << 2);
}

// Interleaved zero: 4 block-strided, fully warp-coalesced STG.128 per thread.
// (R16 showed consecutive-per-thread stores break coalescing: 19.6us; R14's
// 1-store version was 11.8us. This keeps coalescing AND 1/4 thread count.)
__global__ void zero_k(uint4* __restrict__ p, int n4) {
    int S = gridDim.x * blockDim.x;                  // total threads = n4/4
    int i = blockIdx.x * blockDim.x + threadIdx.x;
    uint4 z = make_uint4(0u, 0u, 0u, 0u);
    p[i]         = z;
    p[i + S]     = z;
    p[i + 2 * S] = z;
    p[i + 3 * S] = z;
}

// 4 coords per thread: 3 x int4 streaming loads, 4 fire-and-forget RED.MAX.
// (R1 form; at the REDG spread-address issue floor.)
__global__ void scatter_k(const int4* __restrict__ coords4,
                          unsigned* __restrict__ win) {
    int t = blockIdx.x * blockDim.x + threadIdx.x;   // t < NCOORD/4
    if (t >= NCOORD / 4) return;
    int4 a = __ldcs(coords4 + 3 * t + 0);
    int4 b = __ldcs(coords4 + 3 * t + 1);
    int4 c = __ldcs(coords4 + 3 * t + 2);
    unsigned base = 4u * (unsigned)t;
    unsigned m0 = morton((unsigned)a.x, (unsigned)a.y, (unsigned)a.z);
    unsigned m1 = morton((unsigned)a.w, (unsigned)b.x, (unsigned)b.y);
    unsigned m2 = morton((unsigned)b.z, (unsigned)b.w, (unsigned)c.x);
    unsigned m3 = morton((unsigned)c.y, (unsigned)c.z, (unsigned)c.w);
    // last-write-wins: highest coord index wins (matches sequential scatter)
    atomicMax(win + m0, base + 1u);
    atomicMax(win + m1, base + 2u);
    atomicMax(win + m2, base + 3u);
    atomicMax(win + m3, base + 4u);
}

// R14-form combine: 8 cells/thread, plain loads/stores, hoisted gathers.
template <int FLOATBITS>
__global__ void combine_k(const float* __restrict__ density,
                          const float* __restrict__ sigmas,
                          const unsigned* __restrict__ win,
                          float* __restrict__ out_grid,
                          uint8_t* __restrict__ out_bits_u8,
                          float* __restrict__ out_bits_f) {
    int t = blockIdx.x * blockDim.x + threadIdx.x;   // one byte (8 cells)
    if (t >= GS3 / 8) return;

    uint4 w0 = ((const uint4*)win)[2 * t + 0];
    uint4 w1 = ((const uint4*)win)[2 * t + 1];
    float4 d0 = ((const float4*)density)[2 * t + 0];
    float4 d1 = ((const float4*)density)[2 * t + 1];

    unsigned ws[8] = {w0.x, w0.y, w0.z, w0.w, w1.x, w1.y, w1.z, w1.w};
    float    dv[8] = {d0.x, d0.y, d0.z, d0.w, d1.x, d1.y, d1.z, d1.w};

    // Hoisted gathers: 8 independent predicated loads, maximum gather MLP.
    float sg[8];
#pragma unroll
    for (int b = 0; b < 8; b++)
        sg[b] = ws[b] ? __ldg(sigmas + (ws[b] - 1u)) : -1.0f;

    float    v[8];
    unsigned byte = 0u;
#pragma unroll
    for (int b = 0; b < 8; b++) {
        float val = dv[b];
        if (ws[b]) {
            float s = sg[b];                      // DENSITY_SCALE == 1.0
            if (val >= 0.0f && s >= 0.0f)         // valid = old>=0 && new>=0
                val = fmaxf(0.95f * val, s);      // DECAY = 0.95
        }
        v[b] = val;
        if (val > 0.01f) byte |= (1u << b);       // DENSITY_THRESHOLD = 0.01
    }

    ((float4*)out_grid)[2 * t + 0] = make_float4(v[0], v[1], v[2], v[3]);
    ((float4*)out_grid)[2 * t + 1] = make_float4(v[4], v[5], v[6], v[7]);

    if (FLOATBITS) {
        out_bits_f[t] = (float)byte;
    } else {
        out_bits_u8[t] = (uint8_t)byte;
    }
}

extern "C" void kernel_launch(void* const* d_in, const int* in_sizes, int n_in,
                              void* d_out, int out_size) {
    const float* density = (const float*)d_in[0];   // [3, 256^3] f32
    const float* sigmas  = (const float*)d_in[1];   // [3, NCOORD] f32
    const int*   coords  = (const int*)d_in[2];     // [3, NCOORD, 3] i32

    unsigned* win = nullptr;
    cudaGetSymbolAddress((void**)&win, g_win);

    // Output layout: reference returns (new_grid f32, bitfield u8).
    const long long f32_elems = (long long)TOTAL_CELLS + (long long)BITS_BYTES;
    bool floatbits = ((long long)out_size == f32_elems);

    float*   out_grid = (float*)d_out;
    uint8_t* bits_u8  = (uint8_t*)d_out + (size_t)TOTAL_CELLS * 4;
    float*   bits_f   = (float*)d_out + (size_t)TOTAL_CELLS;

    const int ZB = (GS3 / 16) / 256;     // zero blocks (4 x 16B/thread) = 4096
    const int SB = (NCOORD / 4) / 256;   // scatter blocks (4 coords/thread)
    const int CB = (GS3 / 8) / 256;      // combine blocks (8 cells/thread)

    // Serial per-cascade pipeline on ONE stream — the measured optimum.
    for (int c = 0; c < CASCADES; c++) {
        unsigned*    winc = win + (size_t)c * GS3;
        const float* denc = density + (size_t)c * GS3;
        const float* sigc = sigmas + (size_t)c * NCOORD;
        const int4*  crdc = (const int4*)(coords + (size_t)c * NCOORD * 3);

        zero_k<<<ZB, 256>>>((uint4*)winc, GS3 / 4);
        scatter_k<<<SB, 256>>>(crdc, winc);
        if (floatbits) {
            combine_k<1><<<CB, 256>>>(denc, sigc, winc,
                                      out_grid + (size_t)c * GS3,
                                      nullptr,
                                      bits_f + (size_t)c * (GS3 / 8));
        } else {
            combine_k<0><<<CB, 256>>>(denc, sigc, winc,
                                      out_grid + (size_t)c * GS3,
                                      bits_u8 + (size_t)c * (GS3 / 8),
                                      nullptr);
        }
    }
}